// round 11
// baseline (speedup 1.0000x reference)
#include <cuda_runtime.h>
#include <cuda_fp16.h>
#include <mma.h>

using namespace nvcuda;

#define NMAX 50000
#define NPAD 50176          // 392*128 padding so GEMM tiles stay in-bounds
#define EMAX 1000000
#define HD   128

// ---------------- device scratch (no allocation allowed) ----------------
__device__ __align__(16) __half g_x[NPAD * HD];       // activations x~ (fp16; padding stays 0)
__device__ __align__(16) __half g_hs[NPAD * HD];      // messages hs = x~ @ W (fp16)
__device__ __align__(16) __half g_Bh3[3 * HD * HD];   // weight splits hi (layers 1..3)
__device__ __align__(16) __half g_Bl3[3 * HD * HD];   // weight splits lo
__device__ __align__(16) float  g_s1[NMAX * 3 + 4];
__device__ __align__(16) float  g_dis[NPAD];
__device__ __align__(16) int    g_deg[NMAX];
__device__ __align__(16) int    g_rowptr[NMAX + 1];
__device__ __align__(16) int    g_cursor[NMAX];
__device__ __align__(16) int    g_col[EMAX];
__device__ __align__(16) int    g_bsum[256];
__device__ int g_ct[4];       // grid-sync counters (reset every launch by k_init)

// ---------------- inline edge dtype detection ----------------
// int64 little-endian with node ids < 2^31 => odd 32-bit words of src region are 0.
__device__ __forceinline__ int edges_is64(const int* __restrict__ w) {
    return (w[1] | w[3] | w[5] | w[7]) == 0;
}

// grid-wide sync for co-resident grids (release/acquire via spin counter)
__device__ __forceinline__ void grid_sync(int* ctr, int nblocks) {
    __syncthreads();
    if (threadIdx.x == 0) {
        __threadfence();
        atomicAdd(ctr, 1);
        while (((volatile int*)ctr)[0] < nblocks) {}
    }
    __syncthreads();
    __threadfence();
}

// ---------------- init: weight splits + deg zero + counter reset ----------------
__global__ void k_init(const float* __restrict__ W1, const float* __restrict__ W2,
                       const float* __restrict__ W3, int n) {
    int i = blockIdx.x * blockDim.x + threadIdx.x;
    if (i < 3 * HD * HD) {
        int l = i / (HD * HD), j = i - l * (HD * HD);
        const float* W = (l == 0) ? W1 : (l == 1) ? W2 : W3;
        float v = W[j];
        __half h = __float2half_rn(v);
        g_Bh3[i] = h;
        g_Bl3[i] = __float2half_rn(v - __half2float(h));
    }
    if (i < n) g_deg[i] = 0;
    if (i < 4) g_ct[i] = 0;
}

// ---------------- fused preprocessing: count + scan + fill, one kernel ----------
// 4 edges per thread, decoded ONCE and held in registers across phases.
// Grid must be fully co-resident: 977 blocks of 256 at <=8 blocks/SM.
#define PREP_SCAN_BLOCKS ((NPAD) / 256)   // 196
__global__ __launch_bounds__(256, 8) void k_prep(const int* __restrict__ w,
                                                 const float* __restrict__ pos,
                                                 int E, int n, int nblocks) {
    __shared__ int sh[256];
    __shared__ int s_off;
    int tid = threadIdx.x;
    int bid = blockIdx.x;
    int base = (bid * 256 + tid) * 4;
    int is64 = edges_is64(w);
    int cnt = E - base;
    if (cnt > 4) cnt = 4;

    int s0 = 0, s1v = 0, s2 = 0, s3 = 0;
    int d0 = 0, d1 = 0, d2 = 0, d3 = 0;
    if (cnt == 4) {
        if (is64) {
            int4 sa = *(const int4*)(w + 2 * base);
            int4 sb = *(const int4*)(w + 2 * base + 4);
            int4 da = *(const int4*)(w + 2 * E + 2 * base);
            int4 db = *(const int4*)(w + 2 * E + 2 * base + 4);
            s0 = sa.x; s1v = sa.z; s2 = sb.x; s3 = sb.z;
            d0 = da.x; d1 = da.z; d2 = db.x; d3 = db.z;
        } else {
            int4 sa = *(const int4*)(w + base);
            int4 da = *(const int4*)(w + E + base);
            s0 = sa.x; s1v = sa.y; s2 = sa.z; s3 = sa.w;
            d0 = da.x; d1 = da.y; d2 = da.z; d3 = da.w;
        }
    } else if (cnt > 0) {
        if (cnt > 0) { s0 = is64 ? w[2 * base] : w[base];
                       d0 = is64 ? w[2 * E + 2 * base] : w[E + base]; }
        if (cnt > 1) { s1v = is64 ? w[2 * (base + 1)] : w[base + 1];
                       d1 = is64 ? w[2 * E + 2 * (base + 1)] : w[E + base + 1]; }
        if (cnt > 2) { s2 = is64 ? w[2 * (base + 2)] : w[base + 2];
                       d2 = is64 ? w[2 * E + 2 * (base + 2)] : w[E + base + 2]; }
    }

    // phase A: degree count
    if (cnt > 0) atomicAdd(&g_deg[d0], 1);
    if (cnt > 1) atomicAdd(&g_deg[d1], 1);
    if (cnt > 2) atomicAdd(&g_deg[d2], 1);
    if (cnt > 3) atomicAdd(&g_deg[d3], 1);

    grid_sync(&g_ct[0], nblocks);

    // phase B: block scans over nodes (first 196 blocks), dis + s1
    if (bid < PREP_SCAN_BLOCKS) {
        int i = bid * 256 + tid;
        int v = (i < n) ? g_deg[i] : 0;
        if (i < n) {
            float d = rsqrtf((float)(v + 1));   // +1 self loop
            g_dis[i] = d;
            g_s1[3 * i + 0] = pos[3 * i + 0] * d;
            g_s1[3 * i + 1] = pos[3 * i + 1] * d;
            g_s1[3 * i + 2] = pos[3 * i + 2] * d;
        }
        sh[tid] = v;
        __syncthreads();
#pragma unroll
        for (int off = 1; off < 256; off <<= 1) {
            int t = (tid >= off) ? sh[tid - off] : 0;
            __syncthreads();
            sh[tid] += t;
            __syncthreads();
        }
        if (i < n) g_rowptr[i + 1] = sh[tid];
        if (tid == 255) g_bsum[bid] = sh[255];
    }

    grid_sync(&g_ct[1], nblocks);

    // phase C: add block prefix, init cursor
    if (bid < PREP_SCAN_BLOCKS) {
        if (tid < 32) {
            int pv = 0;
            for (int l = tid; l < bid; l += 32) pv += g_bsum[l];
            for (int off = 16; off; off >>= 1) pv += __shfl_xor_sync(0xFFFFFFFF, pv, off);
            if (tid == 0) s_off = pv;
        }
        __syncthreads();
        int off = s_off;
        int i = bid * 256 + tid;
        if (i < n) {
            int rv = g_rowptr[i + 1] + off;
            g_rowptr[i + 1] = rv;
            if (i + 1 < n) g_cursor[i + 1] = rv;
        }
        if (i == 0) { g_rowptr[0] = 0; g_cursor[0] = 0; }
    }

    grid_sync(&g_ct[2], nblocks);

    // phase D: CSR fill from registers (no edge re-read)
    if (cnt > 0) g_col[atomicAdd(&g_cursor[d0], 1)] = s0;
    if (cnt > 1) g_col[atomicAdd(&g_cursor[d1], 1)] = s1v;
    if (cnt > 2) g_col[atomicAdd(&g_cursor[d2], 1)] = s2;
    if (cnt > 3) g_col[atomicAdd(&g_cursor[d3], 1)] = s3;
}

// ---------------- fused layer 0: warp per node ----------------
__global__ __launch_bounds__(256) void k_layer0(const float* __restrict__ s1,
                                                const float* __restrict__ W0,
                                                const float* __restrict__ b0,
                                                __half* __restrict__ out, int n) {
    __shared__ float sw[3 * HD];
    __shared__ float sb[HD];
    int t = threadIdx.x;
    for (int i = t; i < 3 * HD; i += 256) sw[i] = W0[i];
    if (t < HD) sb[t] = b0[t];
    __syncthreads();
    int warp = (blockIdx.x * 256 + t) >> 5;
    int lane = t & 31;
    if (warp >= n) return;
    int s = g_rowptr[warp], e = g_rowptr[warp + 1];
    float a0 = 0.f, a1 = 0.f, a2 = 0.f;
    for (int i = s + lane; i < e; i += 32) {
        int c = g_col[i];
        a0 += s1[3 * c + 0];
        a1 += s1[3 * c + 1];
        a2 += s1[3 * c + 2];
    }
    for (int off = 16; off; off >>= 1) {
        a0 += __shfl_xor_sync(0xFFFFFFFF, a0, off);
        a1 += __shfl_xor_sync(0xFFFFFFFF, a1, off);
        a2 += __shfl_xor_sync(0xFFFFFFFF, a2, off);
    }
    a0 += s1[3 * warp + 0];            // self loop
    a1 += s1[3 * warp + 1];
    a2 += s1[3 * warp + 2];
    float d = g_dis[warp];
    a0 *= d; a1 *= d; a2 *= d;
    __half2 o[2];
#pragma unroll
    for (int q = 0; q < 2; q++) {
        int j0 = lane * 4 + 2 * q;
        float v0 = a0 * sw[j0] + a1 * sw[HD + j0] + a2 * sw[2 * HD + j0] + sb[j0];
        float v1 = a0 * sw[j0 + 1] + a1 * sw[HD + j0 + 1] + a2 * sw[2 * HD + j0 + 1] + sb[j0 + 1];
        v0 = d * (v0 / (1.0f + __expf(-v0)));
        v1 = d * (v1 / (1.0f + __expf(-v1)));
        o[q] = __floats2half2_rn(v0, v1);
    }
    ((uint2*)out)[warp * 32 + lane] = *(uint2*)o;
}

// ---------------- tensor-core hidden GEMM: hs = x~ @ (Bh+Bl), gmem-direct ----------------
__global__ __launch_bounds__(256) void k_gemm128_tc(const __half* __restrict__ X,
                                                    const __half* __restrict__ Bh,
                                                    const __half* __restrict__ Bl,
                                                    __half* __restrict__ Hout) {
    __shared__ __align__(16) float sOut[8][16 * 16];   // per-warp epilogue bounce

    int m0 = blockIdx.x * 128;
    int t = threadIdx.x;
    int warp = t >> 5;
    int lane = t & 31;
    int wm = warp >> 1;          // 0..3 : 32-row group
    int wn = warp & 1;           // 0..1 : 64-col group

    wmma::fragment<wmma::accumulator, 16, 16, 16, float> c[2][4];
#pragma unroll
    for (int i = 0; i < 2; i++)
#pragma unroll
        for (int j = 0; j < 4; j++) wmma::fill_fragment(c[i][j], 0.0f);

#pragma unroll
    for (int k0 = 0; k0 < HD; k0 += 16) {
        wmma::fragment<wmma::matrix_a, 16, 16, 16, __half, wmma::row_major> a[2];
        wmma::fragment<wmma::matrix_b, 16, 16, 16, __half, wmma::row_major> bH[4], bL[4];
#pragma unroll
        for (int i = 0; i < 2; i++)
            wmma::load_matrix_sync(a[i], X + (m0 + wm * 32 + i * 16) * HD + k0, HD);
#pragma unroll
        for (int j = 0; j < 4; j++) {
            wmma::load_matrix_sync(bH[j], Bh + k0 * HD + wn * 64 + j * 16, HD);
            wmma::load_matrix_sync(bL[j], Bl + k0 * HD + wn * 64 + j * 16, HD);
        }
#pragma unroll
        for (int i = 0; i < 2; i++)
#pragma unroll
            for (int j = 0; j < 4; j++) {
                wmma::mma_sync(c[i][j], a[i], bH[j], c[i][j]);
                wmma::mma_sync(c[i][j], a[i], bL[j], c[i][j]);
            }
    }

#pragma unroll
    for (int i = 0; i < 2; i++)
#pragma unroll
        for (int j = 0; j < 4; j++) {
            wmma::store_matrix_sync(&sOut[warp][0], c[i][j], 16, wmma::mem_row_major);
            __syncwarp();
            int r = lane >> 1;                 // 0..15
            int c8 = (lane & 1) * 8;           // 0 or 8
            const float* srcp = &sOut[warp][r * 16 + c8];
            __half2 o[4];
#pragma unroll
            for (int q = 0; q < 4; q++)
                o[q] = __floats2half2_rn(srcp[2 * q], srcp[2 * q + 1]);
            __half* dst = Hout + (m0 + wm * 32 + i * 16 + r) * HD + wn * 64 + j * 16 + c8;
            *(uint4*)dst = *(uint4*)o;
            __syncwarp();
        }
}

// ---------------- 128-wide aggregation: 16 lanes per node, 8-edge unroll ----------------
__global__ void k_agg128(const __half* __restrict__ hs, const float* __restrict__ bias,
                         __half* __restrict__ out, int n) {
    int gtid = blockIdx.x * blockDim.x + threadIdx.x;
    int node = gtid >> 4;              // 16 lanes per node
    int l16 = gtid & 15;               // this lane's 8 features: [l16*8, l16*8+8)
    if (node >= n) return;
    const uint4* hs4 = (const uint4*)hs;   // 8 halfs per uint4, 16 uint4 per row
    float acc[8];
    {
        uint4 u = hs4[node * 16 + l16];    // self loop
        __half2* hp = (__half2*)&u;
#pragma unroll
        for (int q = 0; q < 4; q++) {
            float2 f = __half22float2(hp[q]);
            acc[2 * q] = f.x; acc[2 * q + 1] = f.y;
        }
    }
    int s = g_rowptr[node], e = g_rowptr[node + 1];
    int i = s;
    // scalar head until 4-aligned index (int4 col loads need 16B alignment)
    int head = (s + 3) & ~3;
    if (head > e) head = e;
    for (; i < head; i++) {
        int c = g_col[i];
        uint4 v = hs4[c * 16 + l16];
        __half2* p = (__half2*)&v;
#pragma unroll
        for (int q = 0; q < 4; q++) {
            float2 f = __half22float2(p[q]);
            acc[2 * q] += f.x; acc[2 * q + 1] += f.y;
        }
    }
    // vectorized body: 8 edges per iter (8 outstanding 16B gathers)
    for (; i + 8 <= e; i += 8) {
        int4 ca = *(const int4*)(g_col + i);
        int4 cb = *(const int4*)(g_col + i + 4);
        uint4 v0 = hs4[ca.x * 16 + l16];
        uint4 v1 = hs4[ca.y * 16 + l16];
        uint4 v2 = hs4[ca.z * 16 + l16];
        uint4 v3 = hs4[ca.w * 16 + l16];
        uint4 v4 = hs4[cb.x * 16 + l16];
        uint4 v5 = hs4[cb.y * 16 + l16];
        uint4 v6 = hs4[cb.z * 16 + l16];
        uint4 v7 = hs4[cb.w * 16 + l16];
        __half2* p0 = (__half2*)&v0; __half2* p1 = (__half2*)&v1;
        __half2* p2 = (__half2*)&v2; __half2* p3 = (__half2*)&v3;
        __half2* p4 = (__half2*)&v4; __half2* p5 = (__half2*)&v5;
        __half2* p6 = (__half2*)&v6; __half2* p7 = (__half2*)&v7;
#pragma unroll
        for (int q = 0; q < 4; q++) {
            __half2 t01 = __hadd2(p0[q], p1[q]);   // one fp16 rounding per pair
            __half2 t23 = __hadd2(p2[q], p3[q]);
            __half2 t45 = __hadd2(p4[q], p5[q]);
            __half2 t67 = __hadd2(p6[q], p7[q]);
            float2 f01 = __half22float2(t01);
            float2 f23 = __half22float2(t23);
            float2 f45 = __half22float2(t45);
            float2 f67 = __half22float2(t67);
            acc[2 * q]     += (f01.x + f23.x) + (f45.x + f67.x);
            acc[2 * q + 1] += (f01.y + f23.y) + (f45.y + f67.y);
        }
    }
    // 4-edge step
    for (; i + 4 <= e; i += 4) {
        int4 cc = *(const int4*)(g_col + i);
        uint4 v0 = hs4[cc.x * 16 + l16];
        uint4 v1 = hs4[cc.y * 16 + l16];
        uint4 v2 = hs4[cc.z * 16 + l16];
        uint4 v3 = hs4[cc.w * 16 + l16];
        __half2* p0 = (__half2*)&v0; __half2* p1 = (__half2*)&v1;
        __half2* p2 = (__half2*)&v2; __half2* p3 = (__half2*)&v3;
#pragma unroll
        for (int q = 0; q < 4; q++) {
            __half2 t01 = __hadd2(p0[q], p1[q]);
            __half2 t23 = __hadd2(p2[q], p3[q]);
            float2 f01 = __half22float2(t01);
            float2 f23 = __half22float2(t23);
            acc[2 * q]     += f01.x + f23.x;
            acc[2 * q + 1] += f01.y + f23.y;
        }
    }
    // scalar tail
    for (; i < e; i++) {
        int c = g_col[i];
        uint4 v = hs4[c * 16 + l16];
        __half2* p = (__half2*)&v;
#pragma unroll
        for (int q = 0; q < 4; q++) {
            float2 f = __half22float2(p[q]);
            acc[2 * q] += f.x; acc[2 * q + 1] += f.y;
        }
    }
    float d = g_dis[node];
    const float4* b4 = (const float4*)bias;
    float4 b0 = b4[l16 * 2], b1 = b4[l16 * 2 + 1];
    float bb[8] = {b0.x, b0.y, b0.z, b0.w, b1.x, b1.y, b1.z, b1.w};
    __half2 o[4];
#pragma unroll
    for (int q = 0; q < 4; q++) {
        float r0 = acc[2 * q] * d + bb[2 * q];
        float r1 = acc[2 * q + 1] * d + bb[2 * q + 1];
        r0 = d * (r0 / (1.0f + __expf(-r0)));
        r1 = d * (r1 / (1.0f + __expf(-r1)));
        o[q] = __floats2half2_rn(r0, r1);
    }
    ((uint4*)out)[node * 16 + l16] = *(uint4*)o;
}

// ---------------- fused tail: hs3 = x~ @ W4, grid-sync, 3-wide agg -> out ---------
#define TAIL_BLOCKS 592
__global__ __launch_bounds__(256) void k_tail(const __half* __restrict__ X,
                                              const float* __restrict__ W4,
                                              const float* __restrict__ bias,
                                              float* __restrict__ s1,
                                              float* __restrict__ out, int n) {
    int t = threadIdx.x;
    int lane = t & 31;
    int nwarps = TAIL_BLOCKS * 8;
    // phase 1: warp per node, hs3 = x~ @ W4 -> s1
    for (int node = (blockIdx.x * 256 + t) >> 5; node < n; node += nwarps) {
        uint2 u = ((const uint2*)X)[node * 32 + lane];
        float2 p0 = __half22float2(*(__half2*)&u.x);
        float2 p1 = __half22float2(*(__half2*)&u.y);
        int k = lane * 4;
        float a0 = p0.x * W4[(k + 0) * 3 + 0] + p0.y * W4[(k + 1) * 3 + 0] +
                   p1.x * W4[(k + 2) * 3 + 0] + p1.y * W4[(k + 3) * 3 + 0];
        float a1 = p0.x * W4[(k + 0) * 3 + 1] + p0.y * W4[(k + 1) * 3 + 1] +
                   p1.x * W4[(k + 2) * 3 + 1] + p1.y * W4[(k + 3) * 3 + 1];
        float a2 = p0.x * W4[(k + 0) * 3 + 2] + p0.y * W4[(k + 1) * 3 + 2] +
                   p1.x * W4[(k + 2) * 3 + 2] + p1.y * W4[(k + 3) * 3 + 2];
        for (int off = 16; off; off >>= 1) {
            a0 += __shfl_xor_sync(0xFFFFFFFF, a0, off);
            a1 += __shfl_xor_sync(0xFFFFFFFF, a1, off);
            a2 += __shfl_xor_sync(0xFFFFFFFF, a2, off);
        }
        if (lane == 0) {
            s1[node * 3 + 0] = a0;
            s1[node * 3 + 1] = a1;
            s1[node * 3 + 2] = a2;
        }
    }
    // grid sync
    __syncthreads();
    if (t == 0) {
        __threadfence();
        atomicAdd(&g_ct[3], 1);
        while (((volatile int*)&g_ct[3])[0] < TAIL_BLOCKS) {}
    }
    __syncthreads();
    __threadfence();
    // phase 2: thread per node, 3-wide aggregate + bias -> out
    float bb0 = bias[0], bb1 = bias[1], bb2 = bias[2];
    for (int node = blockIdx.x * 256 + t; node < n; node += TAIL_BLOCKS * 256) {
        float a0 = s1[node * 3 + 0], a1 = s1[node * 3 + 1], a2 = s1[node * 3 + 2];
        int s = g_rowptr[node], e = g_rowptr[node + 1];
        for (int i = s; i < e; i++) {
            int c = g_col[i];
            a0 += s1[3 * c + 0];
            a1 += s1[3 * c + 1];
            a2 += s1[3 * c + 2];
        }
        float d = g_dis[node];
        out[node * 3 + 0] = a0 * d + bb0;
        out[node * 3 + 1] = a1 * d + bb1;
        out[node * 3 + 2] = a2 * d + bb2;
    }
}

// ---------------- host launch ----------------
extern "C" void kernel_launch(void* const* d_in, const int* in_sizes, int n_in,
                              void* d_out, int out_size) {
    const float* pos = (const float*)d_in[0];
    const int* ei_words = (const int*)d_in[1];
    const float* W[5]; const float* B[5];
    for (int l = 0; l < 5; l++) {
        W[l] = (const float*)d_in[2 + 2 * l];
        B[l] = (const float*)d_in[3 + 2 * l];
    }
    int N = in_sizes[0] / 3;        // 50000
    int E = in_sizes[1] / 2;        // 1000000

    __half *xbuf, *hsbuf, *bh3, *bl3;
    float *s1;
    cudaGetSymbolAddress((void**)&xbuf, g_x);
    cudaGetSymbolAddress((void**)&hsbuf, g_hs);
    cudaGetSymbolAddress((void**)&bh3, g_Bh3);
    cudaGetSymbolAddress((void**)&bl3, g_Bl3);
    cudaGetSymbolAddress((void**)&s1, g_s1);

    // init (wsplit + deg zero + counters)
    k_init<<<(NPAD + 255) / 256, 256>>>(W[1], W[2], W[3], N);

    // fused preprocessing: count + scan + fill in one co-resident kernel
    int prep_blocks = ((E + 3) / 4 + 255) / 256;   // 977 for E=1M (<=1184 resident)
    k_prep<<<prep_blocks, 256>>>(ei_words, pos, E, N, prep_blocks);

    // layer 0 (fused 3-wide agg + dense W0 + bias + silu + dis fold) -> fp16 x~
    k_layer0<<<(N * 32 + 255) / 256, 256>>>(s1, W[0], B[0], xbuf, N);

    // layers 1..3: TC GEMM (pre-split weights) then fp16 aggregation
    int gemm_blocks = NPAD / 128;            // 392
    int agg_blocks = (N * 16 + 255) / 256;   // 16 lanes per node
    for (int l = 1; l <= 3; l++) {
        k_gemm128_tc<<<gemm_blocks, 256>>>(xbuf, bh3 + (l - 1) * HD * HD,
                                           bl3 + (l - 1) * HD * HD, hsbuf);
        k_agg128<<<agg_blocks, 256>>>(hsbuf, B[l], xbuf, N);
    }

    // fused tail: hs3 GEMM + grid sync + 3-wide aggregation -> out
    k_tail<<<TAIL_BLOCKS, 256>>>(xbuf, W[4], B[4], s1, (float*)d_out, N);
}

// round 12
// speedup vs baseline: 1.3867x; 1.3867x over previous
#include <cuda_runtime.h>
#include <cuda_fp16.h>
#include <mma.h>

using namespace nvcuda;

#define NMAX 50000
#define NPAD 50176          // 392*128 padding so GEMM tiles stay in-bounds
#define EMAX 1000000
#define HD   128
#define BPAD 136            // padded smem row (halves) to avoid LDSM bank conflicts

// ---------------- device scratch (no allocation allowed) ----------------
__device__ __align__(16) __half g_x[NPAD * HD];       // activations x~ (fp16; padding stays 0)
__device__ __align__(16) __half g_hs[NPAD * HD];      // messages hs = x~ @ W (fp16)
__device__ __align__(16) __half g_Bh3[3 * HD * HD];   // weight splits hi (layers 1..3)
__device__ __align__(16) __half g_Bl3[3 * HD * HD];   // weight splits lo
__device__ __align__(16) float  g_s1[NMAX * 3 + 4];
__device__ __align__(16) float  g_dis[NPAD];
__device__ __align__(16) int    g_deg[NMAX];
__device__ __align__(16) int    g_rowptr[NMAX + 1];
__device__ __align__(16) int    g_cursor[NMAX];
__device__ __align__(16) int    g_col[EMAX];
__device__ __align__(16) int    g_bsum[64];
__device__ int g_ct[2];       // grid-sync counters (reset every launch by k_init)

// ---------------- inline edge dtype detection ----------------
// int64 little-endian with node ids < 2^31 => odd 32-bit words of src region are 0.
__device__ __forceinline__ int edges_is64(const int* __restrict__ w) {
    return (w[1] | w[3] | w[5] | w[7]) == 0;
}

// ---------------- init: weight splits + deg zero + counter reset ----------------
__global__ void k_init(const float* __restrict__ W1, const float* __restrict__ W2,
                       const float* __restrict__ W3, int n) {
    int i = blockIdx.x * blockDim.x + threadIdx.x;
    if (i < 3 * HD * HD) {
        int l = i / (HD * HD), j = i - l * (HD * HD);
        const float* W = (l == 0) ? W1 : (l == 1) ? W2 : W3;
        float v = W[j];
        __half h = __float2half_rn(v);
        g_Bh3[i] = h;
        g_Bl3[i] = __float2half_rn(v - __half2float(h));
    }
    if (i < n) g_deg[i] = 0;
    if (i < 2) g_ct[i] = 0;
}

// degree count, decoding edges in place (1 edge/thread — latency-optimal per R10)
__global__ void k_count(const int* __restrict__ w, int E) {
    int i = blockIdx.x * blockDim.x + threadIdx.x;
    if (i >= E) return;
    int d = edges_is64(w) ? w[2 * E + 2 * i] : w[E + i];
    atomicAdd(&g_deg[d], 1);
}

// ---------------- fused single-pass scan (grid co-resident: 49 blocks) ----------
__global__ __launch_bounds__(1024) void k_scan(const float* __restrict__ pos, int n) {
    __shared__ int s[1024];
    __shared__ int s_off;
    int tid = threadIdx.x;
    int i = blockIdx.x * 1024 + tid;
    int v = (i < n) ? g_deg[i] : 0;
    if (i < n) {
        float d = rsqrtf((float)(v + 1));   // +1 self loop
        g_dis[i] = d;
        g_s1[3 * i + 0] = pos[3 * i + 0] * d;
        g_s1[3 * i + 1] = pos[3 * i + 1] * d;
        g_s1[3 * i + 2] = pos[3 * i + 2] * d;
    }
    s[tid] = v;
    __syncthreads();
    for (int off = 1; off < 1024; off <<= 1) {
        int t = (tid >= off) ? s[tid - off] : 0;
        __syncthreads();
        s[tid] += t;
        __syncthreads();
    }
    if (tid == 1023) {
        g_bsum[blockIdx.x] = s[1023];
        __threadfence();
        atomicAdd(&g_ct[0], 1);
    }
    if (tid == 0) {
        while (((volatile int*)&g_ct[0])[0] < gridDim.x) {}
    }
    __syncthreads();
    __threadfence();
    if (tid < 32) {
        int l = tid, bid = blockIdx.x;
        int pv = (l < bid) ? g_bsum[l] : 0;
        if (l + 32 < bid) pv += g_bsum[l + 32];
        for (int off = 16; off; off >>= 1) pv += __shfl_xor_sync(0xFFFFFFFF, pv, off);
        if (l == 0) s_off = pv;
    }
    __syncthreads();
    int off = s_off;
    if (i < n) {
        int rv = s[tid] + off;
        g_rowptr[i + 1] = rv;
        if (i + 1 < n) g_cursor[i + 1] = rv;
    }
    if (i == 0) { g_rowptr[0] = 0; g_cursor[0] = 0; }
}

// CSR fill, decoding edges in place (1 edge/thread)
__global__ void k_fill(const int* __restrict__ w, int E) {
    int i = blockIdx.x * blockDim.x + threadIdx.x;
    if (i >= E) return;
    int s, d;
    if (edges_is64(w)) {
        s = w[2 * i];
        d = w[2 * E + 2 * i];
    } else {
        s = w[i];
        d = w[E + i];
    }
    int p = atomicAdd(&g_cursor[d], 1);
    g_col[p] = s;
}

// ---------------- fused layer 0: warp per node ----------------
__global__ __launch_bounds__(256) void k_layer0(const float* __restrict__ s1,
                                                const float* __restrict__ W0,
                                                const float* __restrict__ b0,
                                                __half* __restrict__ out, int n) {
    __shared__ float sw[3 * HD];
    __shared__ float sb[HD];
    int t = threadIdx.x;
    for (int i = t; i < 3 * HD; i += 256) sw[i] = W0[i];
    if (t < HD) sb[t] = b0[t];
    __syncthreads();
    int warp = (blockIdx.x * 256 + t) >> 5;
    int lane = t & 31;
    if (warp >= n) return;
    int s = g_rowptr[warp], e = g_rowptr[warp + 1];
    float a0 = 0.f, a1 = 0.f, a2 = 0.f;
    for (int i = s + lane; i < e; i += 32) {
        int c = g_col[i];
        a0 += s1[3 * c + 0];
        a1 += s1[3 * c + 1];
        a2 += s1[3 * c + 2];
    }
    for (int off = 16; off; off >>= 1) {
        a0 += __shfl_xor_sync(0xFFFFFFFF, a0, off);
        a1 += __shfl_xor_sync(0xFFFFFFFF, a1, off);
        a2 += __shfl_xor_sync(0xFFFFFFFF, a2, off);
    }
    a0 += s1[3 * warp + 0];            // self loop
    a1 += s1[3 * warp + 1];
    a2 += s1[3 * warp + 2];
    float d = g_dis[warp];
    a0 *= d; a1 *= d; a2 *= d;
    __half2 o[2];
#pragma unroll
    for (int q = 0; q < 2; q++) {
        int j0 = lane * 4 + 2 * q;
        float v0 = a0 * sw[j0] + a1 * sw[HD + j0] + a2 * sw[2 * HD + j0] + sb[j0];
        float v1 = a0 * sw[j0 + 1] + a1 * sw[HD + j0 + 1] + a2 * sw[2 * HD + j0 + 1] + sb[j0 + 1];
        v0 = d * (v0 / (1.0f + __expf(-v0)));
        v1 = d * (v1 / (1.0f + __expf(-v1)));
        o[q] = __floats2half2_rn(v0, v1);
    }
    ((uint2*)out)[warp * 32 + lane] = *(uint2*)o;
}

// ---------------- tensor-core hidden GEMM: hs = x~ @ (Bh+Bl) ----------------
// B splits staged ONCE per block in padded smem (no redundant gmem fragment loads).
// A fragments from gmem (2-warp redundancy only). 2 blocks/SM via launch bounds.
__global__ __launch_bounds__(256, 2) void k_gemm128_tc(const __half* __restrict__ X,
                                                       const __half* __restrict__ Bh,
                                                       const __half* __restrict__ Bl,
                                                       __half* __restrict__ Hout) {
    extern __shared__ __align__(16) __half smem[];
    __half* sBh = smem;                  // [128][BPAD]
    __half* sBl = smem + 128 * BPAD;     // [128][BPAD]

    int t = threadIdx.x;
    int warp = t >> 5;
    int lane = t & 31;
    int wm = warp >> 1;          // 0..3 : 32-row group
    int wn = warp & 1;           // 0..1 : 64-col group
    int m0 = blockIdx.x * 128;

    // stage both B splits (coalesced uint4 loads)
#pragma unroll
    for (int q = 0; q < 8; q++) {
        int idx = t + q * 256;           // 0..2047 uint4 slots
        int row = idx >> 4;
        int c16 = (idx & 15) * 8;
        *(uint4*)(sBh + row * BPAD + c16) = *(const uint4*)(Bh + row * HD + c16);
        *(uint4*)(sBl + row * BPAD + c16) = *(const uint4*)(Bl + row * HD + c16);
    }
    __syncthreads();

    wmma::fragment<wmma::accumulator, 16, 16, 16, float> c[2][4];
#pragma unroll
    for (int i = 0; i < 2; i++)
#pragma unroll
        for (int j = 0; j < 4; j++) wmma::fill_fragment(c[i][j], 0.0f);

#pragma unroll
    for (int k0 = 0; k0 < HD; k0 += 16) {
        wmma::fragment<wmma::matrix_a, 16, 16, 16, __half, wmma::row_major> a[2];
#pragma unroll
        for (int i = 0; i < 2; i++)
            wmma::load_matrix_sync(a[i], X + (m0 + wm * 32 + i * 16) * HD + k0, HD);
#pragma unroll
        for (int j = 0; j < 4; j++) {
            wmma::fragment<wmma::matrix_b, 16, 16, 16, __half, wmma::row_major> bH, bL;
            wmma::load_matrix_sync(bH, sBh + k0 * BPAD + wn * 64 + j * 16, BPAD);
            wmma::load_matrix_sync(bL, sBl + k0 * BPAD + wn * 64 + j * 16, BPAD);
            wmma::mma_sync(c[0][j], a[0], bH, c[0][j]);
            wmma::mma_sync(c[1][j], a[1], bH, c[1][j]);
            wmma::mma_sync(c[0][j], a[0], bL, c[0][j]);
            wmma::mma_sync(c[1][j], a[1], bL, c[1][j]);
        }
    }

    // epilogue: fp32 fragment -> fp16 gmem via smem bounce (reuse dynamic smem)
    __syncthreads();
    float* sOut = (float*)smem + warp * 256;
#pragma unroll
    for (int i = 0; i < 2; i++)
#pragma unroll
        for (int j = 0; j < 4; j++) {
            wmma::store_matrix_sync(sOut, c[i][j], 16, wmma::mem_row_major);
            __syncwarp();
            int r = lane >> 1;                 // 0..15
            int c8 = (lane & 1) * 8;           // 0 or 8
            const float* srcp = sOut + r * 16 + c8;
            __half2 o[4];
#pragma unroll
            for (int q = 0; q < 4; q++)
                o[q] = __floats2half2_rn(srcp[2 * q], srcp[2 * q + 1]);
            __half* dst = Hout + (m0 + wm * 32 + i * 16 + r) * HD + wn * 64 + j * 16 + c8;
            *(uint4*)dst = *(uint4*)o;
            __syncwarp();
        }
}

// ---------------- 128-wide aggregation: 16 lanes per node, 8-edge unroll ----------------
__global__ void k_agg128(const __half* __restrict__ hs, const float* __restrict__ bias,
                         __half* __restrict__ out, int n) {
    int gtid = blockIdx.x * blockDim.x + threadIdx.x;
    int node = gtid >> 4;              // 16 lanes per node
    int l16 = gtid & 15;               // this lane's 8 features: [l16*8, l16*8+8)
    if (node >= n) return;
    const uint4* hs4 = (const uint4*)hs;   // 8 halfs per uint4, 16 uint4 per row
    float acc[8];
    {
        uint4 u = hs4[node * 16 + l16];    // self loop
        __half2* hp = (__half2*)&u;
#pragma unroll
        for (int q = 0; q < 4; q++) {
            float2 f = __half22float2(hp[q]);
            acc[2 * q] = f.x; acc[2 * q + 1] = f.y;
        }
    }
    int s = g_rowptr[node], e = g_rowptr[node + 1];
    int i = s;
    int head = (s + 3) & ~3;
    if (head > e) head = e;
    for (; i < head; i++) {
        int c = g_col[i];
        uint4 v = hs4[c * 16 + l16];
        __half2* p = (__half2*)&v;
#pragma unroll
        for (int q = 0; q < 4; q++) {
            float2 f = __half22float2(p[q]);
            acc[2 * q] += f.x; acc[2 * q + 1] += f.y;
        }
    }
    for (; i + 8 <= e; i += 8) {
        int4 ca = *(const int4*)(g_col + i);
        int4 cb = *(const int4*)(g_col + i + 4);
        uint4 v0 = hs4[ca.x * 16 + l16];
        uint4 v1 = hs4[ca.y * 16 + l16];
        uint4 v2 = hs4[ca.z * 16 + l16];
        uint4 v3 = hs4[ca.w * 16 + l16];
        uint4 v4 = hs4[cb.x * 16 + l16];
        uint4 v5 = hs4[cb.y * 16 + l16];
        uint4 v6 = hs4[cb.z * 16 + l16];
        uint4 v7 = hs4[cb.w * 16 + l16];
        __half2* p0 = (__half2*)&v0; __half2* p1 = (__half2*)&v1;
        __half2* p2 = (__half2*)&v2; __half2* p3 = (__half2*)&v3;
        __half2* p4 = (__half2*)&v4; __half2* p5 = (__half2*)&v5;
        __half2* p6 = (__half2*)&v6; __half2* p7 = (__half2*)&v7;
#pragma unroll
        for (int q = 0; q < 4; q++) {
            __half2 t01 = __hadd2(p0[q], p1[q]);   // one fp16 rounding per pair
            __half2 t23 = __hadd2(p2[q], p3[q]);
            __half2 t45 = __hadd2(p4[q], p5[q]);
            __half2 t67 = __hadd2(p6[q], p7[q]);
            float2 f01 = __half22float2(t01);
            float2 f23 = __half22float2(t23);
            float2 f45 = __half22float2(t45);
            float2 f67 = __half22float2(t67);
            acc[2 * q]     += (f01.x + f23.x) + (f45.x + f67.x);
            acc[2 * q + 1] += (f01.y + f23.y) + (f45.y + f67.y);
        }
    }
    for (; i + 4 <= e; i += 4) {
        int4 cc = *(const int4*)(g_col + i);
        uint4 v0 = hs4[cc.x * 16 + l16];
        uint4 v1 = hs4[cc.y * 16 + l16];
        uint4 v2 = hs4[cc.z * 16 + l16];
        uint4 v3 = hs4[cc.w * 16 + l16];
        __half2* p0 = (__half2*)&v0; __half2* p1 = (__half2*)&v1;
        __half2* p2 = (__half2*)&v2; __half2* p3 = (__half2*)&v3;
#pragma unroll
        for (int q = 0; q < 4; q++) {
            __half2 t01 = __hadd2(p0[q], p1[q]);
            __half2 t23 = __hadd2(p2[q], p3[q]);
            float2 f01 = __half22float2(t01);
            float2 f23 = __half22float2(t23);
            acc[2 * q]     += f01.x + f23.x;
            acc[2 * q + 1] += f01.y + f23.y;
        }
    }
    for (; i < e; i++) {
        int c = g_col[i];
        uint4 v = hs4[c * 16 + l16];
        __half2* p = (__half2*)&v;
#pragma unroll
        for (int q = 0; q < 4; q++) {
            float2 f = __half22float2(p[q]);
            acc[2 * q] += f.x; acc[2 * q + 1] += f.y;
        }
    }
    float d = g_dis[node];
    const float4* b4 = (const float4*)bias;
    float4 b0 = b4[l16 * 2], b1 = b4[l16 * 2 + 1];
    float bb[8] = {b0.x, b0.y, b0.z, b0.w, b1.x, b1.y, b1.z, b1.w};
    __half2 o[4];
#pragma unroll
    for (int q = 0; q < 4; q++) {
        float r0 = acc[2 * q] * d + bb[2 * q];
        float r1 = acc[2 * q + 1] * d + bb[2 * q + 1];
        r0 = d * (r0 / (1.0f + __expf(-r0)));
        r1 = d * (r1 / (1.0f + __expf(-r1)));
        o[q] = __floats2half2_rn(r0, r1);
    }
    ((uint4*)out)[node * 16 + l16] = *(uint4*)o;
}

// ---------------- fused tail: hs3 = x~ @ W4, grid-sync, 3-wide agg -> out ---------
#define TAIL_BLOCKS 592
__global__ __launch_bounds__(256) void k_tail(const __half* __restrict__ X,
                                              const float* __restrict__ W4,
                                              const float* __restrict__ bias,
                                              float* __restrict__ s1,
                                              float* __restrict__ out, int n) {
    int t = threadIdx.x;
    int lane = t & 31;
    int nwarps = TAIL_BLOCKS * 8;
    for (int node = (blockIdx.x * 256 + t) >> 5; node < n; node += nwarps) {
        uint2 u = ((const uint2*)X)[node * 32 + lane];
        float2 p0 = __half22float2(*(__half2*)&u.x);
        float2 p1 = __half22float2(*(__half2*)&u.y);
        int k = lane * 4;
        float a0 = p0.x * W4[(k + 0) * 3 + 0] + p0.y * W4[(k + 1) * 3 + 0] +
                   p1.x * W4[(k + 2) * 3 + 0] + p1.y * W4[(k + 3) * 3 + 0];
        float a1 = p0.x * W4[(k + 0) * 3 + 1] + p0.y * W4[(k + 1) * 3 + 1] +
                   p1.x * W4[(k + 2) * 3 + 1] + p1.y * W4[(k + 3) * 3 + 1];
        float a2 = p0.x * W4[(k + 0) * 3 + 2] + p0.y * W4[(k + 1) * 3 + 2] +
                   p1.x * W4[(k + 2) * 3 + 2] + p1.y * W4[(k + 3) * 3 + 2];
        for (int off = 16; off; off >>= 1) {
            a0 += __shfl_xor_sync(0xFFFFFFFF, a0, off);
            a1 += __shfl_xor_sync(0xFFFFFFFF, a1, off);
            a2 += __shfl_xor_sync(0xFFFFFFFF, a2, off);
        }
        if (lane == 0) {
            s1[node * 3 + 0] = a0;
            s1[node * 3 + 1] = a1;
            s1[node * 3 + 2] = a2;
        }
    }
    __syncthreads();
    if (t == 0) {
        __threadfence();
        atomicAdd(&g_ct[1], 1);
        while (((volatile int*)&g_ct[1])[0] < TAIL_BLOCKS) {}
    }
    __syncthreads();
    __threadfence();
    float bb0 = bias[0], bb1 = bias[1], bb2 = bias[2];
    for (int node = blockIdx.x * 256 + t; node < n; node += TAIL_BLOCKS * 256) {
        float a0 = s1[node * 3 + 0], a1 = s1[node * 3 + 1], a2 = s1[node * 3 + 2];
        int s = g_rowptr[node], e = g_rowptr[node + 1];
        for (int i = s; i < e; i++) {
            int c = g_col[i];
            a0 += s1[3 * c + 0];
            a1 += s1[3 * c + 1];
            a2 += s1[3 * c + 2];
        }
        float d = g_dis[node];
        out[node * 3 + 0] = a0 * d + bb0;
        out[node * 3 + 1] = a1 * d + bb1;
        out[node * 3 + 2] = a2 * d + bb2;
    }
}

// ---------------- host launch ----------------
extern "C" void kernel_launch(void* const* d_in, const int* in_sizes, int n_in,
                              void* d_out, int out_size) {
    const float* pos = (const float*)d_in[0];
    const int* ei_words = (const int*)d_in[1];
    const float* W[5]; const float* B[5];
    for (int l = 0; l < 5; l++) {
        W[l] = (const float*)d_in[2 + 2 * l];
        B[l] = (const float*)d_in[3 + 2 * l];
    }
    int N = in_sizes[0] / 3;        // 50000
    int E = in_sizes[1] / 2;        // 1000000

    __half *xbuf, *hsbuf, *bh3, *bl3;
    float *s1;
    cudaGetSymbolAddress((void**)&xbuf, g_x);
    cudaGetSymbolAddress((void**)&hsbuf, g_hs);
    cudaGetSymbolAddress((void**)&bh3, g_Bh3);
    cudaGetSymbolAddress((void**)&bl3, g_Bl3);
    cudaGetSymbolAddress((void**)&s1, g_s1);

    int NB = (N + 1023) / 1024;     // 49
    const int GEMM_SMEM = 2 * 128 * BPAD * 2;   // 69632 bytes

    static int smem_set = 0;
    if (!smem_set) {
        cudaFuncSetAttribute(k_gemm128_tc,
                             cudaFuncAttributeMaxDynamicSharedMemorySize, GEMM_SMEM);
        smem_set = 1;
    }

    // init (wsplit + deg zero + counters), degree count
    k_init<<<(NPAD + 255) / 256, 256>>>(W[1], W[2], W[3], N);
    k_count<<<(E + 255) / 256, 256>>>(ei_words, E);

    // fused scan (rowptr/cursor/dis/s1), CSR fill
    k_scan<<<NB, 1024>>>(pos, N);
    k_fill<<<(E + 255) / 256, 256>>>(ei_words, E);

    // layer 0 (fused 3-wide agg + dense W0 + bias + silu + dis fold) -> fp16 x~
    k_layer0<<<(N * 32 + 255) / 256, 256>>>(s1, W[0], B[0], xbuf, N);

    // layers 1..3: TC GEMM (smem-staged B splits) then fp16 aggregation
    int gemm_blocks = NPAD / 128;            // 392
    int agg_blocks = (N * 16 + 255) / 256;   // 16 lanes per node
    for (int l = 1; l <= 3; l++) {
        k_gemm128_tc<<<gemm_blocks, 256, GEMM_SMEM>>>(xbuf, bh3 + (l - 1) * HD * HD,
                                                      bl3 + (l - 1) * HD * HD, hsbuf);
        k_agg128<<<agg_blocks, 256>>>(hsbuf, B[l], xbuf, N);
    }

    // fused tail: hs3 GEMM + grid sync + 3-wide aggregation -> out
    k_tail<<<TAIL_BLOCKS, 256>>>(xbuf, W[4], B[4], s1, (float*)d_out, N);
}

// round 13
// speedup vs baseline: 1.4149x; 1.0203x over previous
#include <cuda_runtime.h>
#include <cuda_fp16.h>
#include <mma.h>

using namespace nvcuda;

#define NMAX 50000
#define NPAD 50176          // 392*128 padding so GEMM tiles stay in-bounds
#define EMAX 1000000
#define HD   128
#define BPAD 136            // padded smem row (halves): B fragment rows 4-bank step
#define APAD 24             // padded A slice row (halves): 48B rows, 16B-aligned, conflict-free LDSM

// ---------------- device scratch (no allocation allowed) ----------------
__device__ __align__(16) __half g_x[NPAD * HD];       // activations x~ (fp16; padding stays 0)
__device__ __align__(16) __half g_hs[NPAD * HD];      // messages hs = x~ @ W (fp16)
__device__ __align__(16) __half g_Bh3[3 * HD * HD];   // weight splits hi (layers 1..3)
__device__ __align__(16) __half g_Bl3[3 * HD * HD];   // weight splits lo
__device__ __align__(16) float  g_s1[NMAX * 3 + 4];
__device__ __align__(16) float  g_dis[NPAD];
__device__ __align__(16) int    g_deg[NMAX];
__device__ __align__(16) int    g_rowptr[NMAX + 1];
__device__ __align__(16) int    g_cursor[NMAX];
__device__ __align__(16) int    g_col[EMAX];
__device__ __align__(16) int    g_bsum[64];
__device__ int g_ct[2];       // grid-sync counters (reset every launch by k_init)

// ---------------- inline edge dtype detection ----------------
__device__ __forceinline__ int edges_is64(const int* __restrict__ w) {
    return (w[1] | w[3] | w[5] | w[7]) == 0;
}

// ---------------- cp.async helpers ----------------
__device__ __forceinline__ void cp_async16(void* smem_dst, const void* gmem_src) {
    unsigned sa = (unsigned)__cvta_generic_to_shared(smem_dst);
    asm volatile("cp.async.ca.shared.global [%0], [%1], 16;" :: "r"(sa), "l"(gmem_src));
}
__device__ __forceinline__ void cp_async_commit() {
    asm volatile("cp.async.commit_group;");
}
template <int N>
__device__ __forceinline__ void cp_async_wait() {
    asm volatile("cp.async.wait_group %0;" :: "n"(N));
}

// ---------------- init: weight splits + deg zero + counter reset ----------------
__global__ void k_init(const float* __restrict__ W1, const float* __restrict__ W2,
                       const float* __restrict__ W3, int n) {
    int i = blockIdx.x * blockDim.x + threadIdx.x;
    if (i < 3 * HD * HD) {
        int l = i / (HD * HD), j = i - l * (HD * HD);
        const float* W = (l == 0) ? W1 : (l == 1) ? W2 : W3;
        float v = W[j];
        __half h = __float2half_rn(v);
        g_Bh3[i] = h;
        g_Bl3[i] = __float2half_rn(v - __half2float(h));
    }
    if (i < n) g_deg[i] = 0;
    if (i < 2) g_ct[i] = 0;
}

// degree count, decoding edges in place
__global__ void k_count(const int* __restrict__ w, int E) {
    int i = blockIdx.x * blockDim.x + threadIdx.x;
    if (i >= E) return;
    int d = edges_is64(w) ? w[2 * E + 2 * i] : w[E + i];
    atomicAdd(&g_deg[d], 1);
}

// ---------------- fused single-pass scan (grid co-resident: 49 blocks) ----------
__global__ __launch_bounds__(1024) void k_scan(const float* __restrict__ pos, int n) {
    __shared__ int s[1024];
    __shared__ int s_off;
    int tid = threadIdx.x;
    int i = blockIdx.x * 1024 + tid;
    int v = (i < n) ? g_deg[i] : 0;
    if (i < n) {
        float d = rsqrtf((float)(v + 1));   // +1 self loop
        g_dis[i] = d;
        g_s1[3 * i + 0] = pos[3 * i + 0] * d;
        g_s1[3 * i + 1] = pos[3 * i + 1] * d;
        g_s1[3 * i + 2] = pos[3 * i + 2] * d;
    }
    s[tid] = v;
    __syncthreads();
    for (int off = 1; off < 1024; off <<= 1) {
        int t = (tid >= off) ? s[tid - off] : 0;
        __syncthreads();
        s[tid] += t;
        __syncthreads();
    }
    if (tid == 1023) {
        g_bsum[blockIdx.x] = s[1023];
        __threadfence();
        atomicAdd(&g_ct[0], 1);
    }
    if (tid == 0) {
        while (((volatile int*)&g_ct[0])[0] < gridDim.x) {}
    }
    __syncthreads();
    __threadfence();
    if (tid < 32) {
        int l = tid, bid = blockIdx.x;
        int pv = (l < bid) ? g_bsum[l] : 0;
        if (l + 32 < bid) pv += g_bsum[l + 32];
        for (int off = 16; off; off >>= 1) pv += __shfl_xor_sync(0xFFFFFFFF, pv, off);
        if (l == 0) s_off = pv;
    }
    __syncthreads();
    int off = s_off;
    if (i < n) {
        int rv = s[tid] + off;
        g_rowptr[i + 1] = rv;
        if (i + 1 < n) g_cursor[i + 1] = rv;
    }
    if (i == 0) { g_rowptr[0] = 0; g_cursor[0] = 0; }
}

// CSR fill, decoding edges in place
__global__ void k_fill(const int* __restrict__ w, int E) {
    int i = blockIdx.x * blockDim.x + threadIdx.x;
    if (i >= E) return;
    int s, d;
    if (edges_is64(w)) {
        s = w[2 * i];
        d = w[2 * E + 2 * i];
    } else {
        s = w[i];
        d = w[E + i];
    }
    int p = atomicAdd(&g_cursor[d], 1);
    g_col[p] = s;
}

// ---------------- fused layer 0: warp per node ----------------
__global__ __launch_bounds__(256) void k_layer0(const float* __restrict__ s1,
                                                const float* __restrict__ W0,
                                                const float* __restrict__ b0,
                                                __half* __restrict__ out, int n) {
    __shared__ float sw[3 * HD];
    __shared__ float sb[HD];
    int t = threadIdx.x;
    for (int i = t; i < 3 * HD; i += 256) sw[i] = W0[i];
    if (t < HD) sb[t] = b0[t];
    __syncthreads();
    int warp = (blockIdx.x * 256 + t) >> 5;
    int lane = t & 31;
    if (warp >= n) return;
    int s = g_rowptr[warp], e = g_rowptr[warp + 1];
    float a0 = 0.f, a1 = 0.f, a2 = 0.f;
    for (int i = s + lane; i < e; i += 32) {
        int c = g_col[i];
        a0 += s1[3 * c + 0];
        a1 += s1[3 * c + 1];
        a2 += s1[3 * c + 2];
    }
    for (int off = 16; off; off >>= 1) {
        a0 += __shfl_xor_sync(0xFFFFFFFF, a0, off);
        a1 += __shfl_xor_sync(0xFFFFFFFF, a1, off);
        a2 += __shfl_xor_sync(0xFFFFFFFF, a2, off);
    }
    a0 += s1[3 * warp + 0];            // self loop
    a1 += s1[3 * warp + 1];
    a2 += s1[3 * warp + 2];
    float d = g_dis[warp];
    a0 *= d; a1 *= d; a2 *= d;
    __half2 o[2];
#pragma unroll
    for (int q = 0; q < 2; q++) {
        int j0 = lane * 4 + 2 * q;
        float v0 = a0 * sw[j0] + a1 * sw[HD + j0] + a2 * sw[2 * HD + j0] + sb[j0];
        float v1 = a0 * sw[j0 + 1] + a1 * sw[HD + j0 + 1] + a2 * sw[2 * HD + j0 + 1] + sb[j0 + 1];
        v0 = d * (v0 / (1.0f + __expf(-v0)));
        v1 = d * (v1 / (1.0f + __expf(-v1)));
        o[q] = __floats2half2_rn(v0, v1);
    }
    ((uint2*)out)[warp * 32 + lane] = *(uint2*)o;
}

// ---------------- tensor-core hidden GEMM: hs = x~ @ (Bh+Bl) ----------------
// B splits staged once per block (padded smem); A k-slices cp.async double-buffered.
// All fragment loads from smem; A read from gmem exactly once per block.
__global__ __launch_bounds__(256, 2) void k_gemm128_tc(const __half* __restrict__ X,
                                                       const __half* __restrict__ Bh,
                                                       const __half* __restrict__ Bl,
                                                       __half* __restrict__ Hout) {
    extern __shared__ __align__(16) __half smem[];
    __half* sBh = smem;                       // [128][BPAD]
    __half* sBl = smem + 128 * BPAD;          // [128][BPAD]
    __half* sA  = smem + 2 * 128 * BPAD;      // [2][128][APAD]

    int t = threadIdx.x;
    int warp = t >> 5;
    int lane = t & 31;
    int wm = warp >> 1;          // 0..3 : 32-row group
    int wn = warp & 1;           // 0..1 : 64-col group
    int m0 = blockIdx.x * 128;

    // A slice prefetch: thread t covers row t>>1, 8-half chunk t&1
    int arow = t >> 1;
    int ac8 = (t & 1) * 8;
    const __half* ag = X + (m0 + arow) * HD + ac8;   // + k0 per slice
    __half* as = sA + arow * APAD + ac8;             // + buf*128*APAD

    // issue first A slice (k0 = 0)
    cp_async16(as, ag);
    cp_async_commit();

    // stage both B splits (coalesced uint4 loads)
#pragma unroll
    for (int q = 0; q < 8; q++) {
        int idx = t + q * 256;           // 0..2047 uint4 slots
        int row = idx >> 4;
        int c16 = (idx & 15) * 8;
        *(uint4*)(sBh + row * BPAD + c16) = *(const uint4*)(Bh + row * HD + c16);
        *(uint4*)(sBl + row * BPAD + c16) = *(const uint4*)(Bl + row * HD + c16);
    }

    wmma::fragment<wmma::accumulator, 16, 16, 16, float> c[2][4];
#pragma unroll
    for (int i = 0; i < 2; i++)
#pragma unroll
        for (int j = 0; j < 4; j++) wmma::fill_fragment(c[i][j], 0.0f);

#pragma unroll
    for (int ks = 0; ks < 8; ks++) {
        // prefetch next A slice into the other buffer
        if (ks < 7) {
            cp_async16(sA + ((ks + 1) & 1) * 128 * APAD + arow * APAD + ac8,
                       ag + (ks + 1) * 16);
            cp_async_commit();
            cp_async_wait<1>();    // current slice (and B on ks=0) complete
        } else {
            cp_async_wait<0>();
        }
        __syncthreads();

        const __half* sAc = sA + (ks & 1) * 128 * APAD;
        int k0 = ks * 16;
        wmma::fragment<wmma::matrix_a, 16, 16, 16, __half, wmma::row_major> a[2];
#pragma unroll
        for (int i = 0; i < 2; i++)
            wmma::load_matrix_sync(a[i], sAc + (wm * 32 + i * 16) * APAD, APAD);
#pragma unroll
        for (int j = 0; j < 4; j++) {
            wmma::fragment<wmma::matrix_b, 16, 16, 16, __half, wmma::row_major> bH, bL;
            wmma::load_matrix_sync(bH, sBh + k0 * BPAD + wn * 64 + j * 16, BPAD);
            wmma::load_matrix_sync(bL, sBl + k0 * BPAD + wn * 64 + j * 16, BPAD);
            wmma::mma_sync(c[0][j], a[0], bH, c[0][j]);
            wmma::mma_sync(c[1][j], a[1], bH, c[1][j]);
            wmma::mma_sync(c[0][j], a[0], bL, c[0][j]);
            wmma::mma_sync(c[1][j], a[1], bL, c[1][j]);
        }
        __syncthreads();
    }

    // epilogue: fp32 fragment -> fp16 gmem via smem bounce (reuse dynamic smem)
    float* sOut = (float*)smem + warp * 256;
#pragma unroll
    for (int i = 0; i < 2; i++)
#pragma unroll
        for (int j = 0; j < 4; j++) {
            wmma::store_matrix_sync(sOut, c[i][j], 16, wmma::mem_row_major);
            __syncwarp();
            int r = lane >> 1;                 // 0..15
            int c8 = (lane & 1) * 8;           // 0 or 8
            const float* srcp = sOut + r * 16 + c8;
            __half2 o[4];
#pragma unroll
            for (int q = 0; q < 4; q++)
                o[q] = __floats2half2_rn(srcp[2 * q], srcp[2 * q + 1]);
            __half* dst = Hout + (m0 + wm * 32 + i * 16 + r) * HD + wn * 64 + j * 16 + c8;
            *(uint4*)dst = *(uint4*)o;
            __syncwarp();
        }
}

// ---------------- 128-wide aggregation: 16 lanes per node, 8-edge unroll ----------------
__global__ void k_agg128(const __half* __restrict__ hs, const float* __restrict__ bias,
                         __half* __restrict__ out, int n) {
    int gtid = blockIdx.x * blockDim.x + threadIdx.x;
    int node = gtid >> 4;              // 16 lanes per node
    int l16 = gtid & 15;               // this lane's 8 features: [l16*8, l16*8+8)
    if (node >= n) return;
    const uint4* hs4 = (const uint4*)hs;   // 8 halfs per uint4, 16 uint4 per row
    float acc[8];
    {
        uint4 u = hs4[node * 16 + l16];    // self loop
        __half2* hp = (__half2*)&u;
#pragma unroll
        for (int q = 0; q < 4; q++) {
            float2 f = __half22float2(hp[q]);
            acc[2 * q] = f.x; acc[2 * q + 1] = f.y;
        }
    }
    int s = g_rowptr[node], e = g_rowptr[node + 1];
    int i = s;
    int head = (s + 3) & ~3;
    if (head > e) head = e;
    for (; i < head; i++) {
        int c = g_col[i];
        uint4 v = hs4[c * 16 + l16];
        __half2* p = (__half2*)&v;
#pragma unroll
        for (int q = 0; q < 4; q++) {
            float2 f = __half22float2(p[q]);
            acc[2 * q] += f.x; acc[2 * q + 1] += f.y;
        }
    }
    for (; i + 8 <= e; i += 8) {
        int4 ca = *(const int4*)(g_col + i);
        int4 cb = *(const int4*)(g_col + i + 4);
        uint4 v0 = hs4[ca.x * 16 + l16];
        uint4 v1 = hs4[ca.y * 16 + l16];
        uint4 v2 = hs4[ca.z * 16 + l16];
        uint4 v3 = hs4[ca.w * 16 + l16];
        uint4 v4 = hs4[cb.x * 16 + l16];
        uint4 v5 = hs4[cb.y * 16 + l16];
        uint4 v6 = hs4[cb.z * 16 + l16];
        uint4 v7 = hs4[cb.w * 16 + l16];
        __half2* p0 = (__half2*)&v0; __half2* p1 = (__half2*)&v1;
        __half2* p2 = (__half2*)&v2; __half2* p3 = (__half2*)&v3;
        __half2* p4 = (__half2*)&v4; __half2* p5 = (__half2*)&v5;
        __half2* p6 = (__half2*)&v6; __half2* p7 = (__half2*)&v7;
#pragma unroll
        for (int q = 0; q < 4; q++) {
            __half2 t01 = __hadd2(p0[q], p1[q]);   // one fp16 rounding per pair
            __half2 t23 = __hadd2(p2[q], p3[q]);
            __half2 t45 = __hadd2(p4[q], p5[q]);
            __half2 t67 = __hadd2(p6[q], p7[q]);
            float2 f01 = __half22float2(t01);
            float2 f23 = __half22float2(t23);
            float2 f45 = __half22float2(t45);
            float2 f67 = __half22float2(t67);
            acc[2 * q]     += (f01.x + f23.x) + (f45.x + f67.x);
            acc[2 * q + 1] += (f01.y + f23.y) + (f45.y + f67.y);
        }
    }
    for (; i + 4 <= e; i += 4) {
        int4 cc = *(const int4*)(g_col + i);
        uint4 v0 = hs4[cc.x * 16 + l16];
        uint4 v1 = hs4[cc.y * 16 + l16];
        uint4 v2 = hs4[cc.z * 16 + l16];
        uint4 v3 = hs4[cc.w * 16 + l16];
        __half2* p0 = (__half2*)&v0; __half2* p1 = (__half2*)&v1;
        __half2* p2 = (__half2*)&v2; __half2* p3 = (__half2*)&v3;
#pragma unroll
        for (int q = 0; q < 4; q++) {
            __half2 t01 = __hadd2(p0[q], p1[q]);
            __half2 t23 = __hadd2(p2[q], p3[q]);
            float2 f01 = __half22float2(t01);
            float2 f23 = __half22float2(t23);
            acc[2 * q]     += f01.x + f23.x;
            acc[2 * q + 1] += f01.y + f23.y;
        }
    }
    for (; i < e; i++) {
        int c = g_col[i];
        uint4 v = hs4[c * 16 + l16];
        __half2* p = (__half2*)&v;
#pragma unroll
        for (int q = 0; q < 4; q++) {
            float2 f = __half22float2(p[q]);
            acc[2 * q] += f.x; acc[2 * q + 1] += f.y;
        }
    }
    float d = g_dis[node];
    const float4* b4 = (const float4*)bias;
    float4 b0 = b4[l16 * 2], b1 = b4[l16 * 2 + 1];
    float bb[8] = {b0.x, b0.y, b0.z, b0.w, b1.x, b1.y, b1.z, b1.w};
    __half2 o[4];
#pragma unroll
    for (int q = 0; q < 4; q++) {
        float r0 = acc[2 * q] * d + bb[2 * q];
        float r1 = acc[2 * q + 1] * d + bb[2 * q + 1];
        r0 = d * (r0 / (1.0f + __expf(-r0)));
        r1 = d * (r1 / (1.0f + __expf(-r1)));
        o[q] = __floats2half2_rn(r0, r1);
    }
    ((uint4*)out)[node * 16 + l16] = *(uint4*)o;
}

// ---------------- fused tail: hs3 = x~ @ W4, grid-sync, 3-wide agg -> out ---------
#define TAIL_BLOCKS 592
__global__ __launch_bounds__(256) void k_tail(const __half* __restrict__ X,
                                              const float* __restrict__ W4,
                                              const float* __restrict__ bias,
                                              float* __restrict__ s1,
                                              float* __restrict__ out, int n) {
    int t = threadIdx.x;
    int lane = t & 31;
    int nwarps = TAIL_BLOCKS * 8;
    for (int node = (blockIdx.x * 256 + t) >> 5; node < n; node += nwarps) {
        uint2 u = ((const uint2*)X)[node * 32 + lane];
        float2 p0 = __half22float2(*(__half2*)&u.x);
        float2 p1 = __half22float2(*(__half2*)&u.y);
        int k = lane * 4;
        float a0 = p0.x * W4[(k + 0) * 3 + 0] + p0.y * W4[(k + 1) * 3 + 0] +
                   p1.x * W4[(k + 2) * 3 + 0] + p1.y * W4[(k + 3) * 3 + 0];
        float a1 = p0.x * W4[(k + 0) * 3 + 1] + p0.y * W4[(k + 1) * 3 + 1] +
                   p1.x * W4[(k + 2) * 3 + 1] + p1.y * W4[(k + 3) * 3 + 1];
        float a2 = p0.x * W4[(k + 0) * 3 + 2] + p0.y * W4[(k + 1) * 3 + 2] +
                   p1.x * W4[(k + 2) * 3 + 2] + p1.y * W4[(k + 3) * 3 + 2];
        for (int off = 16; off; off >>= 1) {
            a0 += __shfl_xor_sync(0xFFFFFFFF, a0, off);
            a1 += __shfl_xor_sync(0xFFFFFFFF, a1, off);
            a2 += __shfl_xor_sync(0xFFFFFFFF, a2, off);
        }
        if (lane == 0) {
            s1[node * 3 + 0] = a0;
            s1[node * 3 + 1] = a1;
            s1[node * 3 + 2] = a2;
        }
    }
    __syncthreads();
    if (t == 0) {
        __threadfence();
        atomicAdd(&g_ct[1], 1);
        while (((volatile int*)&g_ct[1])[0] < TAIL_BLOCKS) {}
    }
    __syncthreads();
    __threadfence();
    float bb0 = bias[0], bb1 = bias[1], bb2 = bias[2];
    for (int node = blockIdx.x * 256 + t; node < n; node += TAIL_BLOCKS * 256) {
        float a0 = s1[node * 3 + 0], a1 = s1[node * 3 + 1], a2 = s1[node * 3 + 2];
        int s = g_rowptr[node], e = g_rowptr[node + 1];
        for (int i = s; i < e; i++) {
            int c = g_col[i];
            a0 += s1[3 * c + 0];
            a1 += s1[3 * c + 1];
            a2 += s1[3 * c + 2];
        }
        float d = g_dis[node];
        out[node * 3 + 0] = a0 * d + bb0;
        out[node * 3 + 1] = a1 * d + bb1;
        out[node * 3 + 2] = a2 * d + bb2;
    }
}

// ---------------- host launch ----------------
extern "C" void kernel_launch(void* const* d_in, const int* in_sizes, int n_in,
                              void* d_out, int out_size) {
    const float* pos = (const float*)d_in[0];
    const int* ei_words = (const int*)d_in[1];
    const float* W[5]; const float* B[5];
    for (int l = 0; l < 5; l++) {
        W[l] = (const float*)d_in[2 + 2 * l];
        B[l] = (const float*)d_in[3 + 2 * l];
    }
    int N = in_sizes[0] / 3;        // 50000
    int E = in_sizes[1] / 2;        // 1000000

    __half *xbuf, *hsbuf, *bh3, *bl3;
    float *s1;
    cudaGetSymbolAddress((void**)&xbuf, g_x);
    cudaGetSymbolAddress((void**)&hsbuf, g_hs);
    cudaGetSymbolAddress((void**)&bh3, g_Bh3);
    cudaGetSymbolAddress((void**)&bl3, g_Bl3);
    cudaGetSymbolAddress((void**)&s1, g_s1);

    int NB = (N + 1023) / 1024;     // 49
    const int GEMM_SMEM = (2 * 128 * BPAD + 2 * 128 * APAD) * 2;   // 81920 bytes

    static int smem_set = 0;
    if (!smem_set) {
        cudaFuncSetAttribute(k_gemm128_tc,
                             cudaFuncAttributeMaxDynamicSharedMemorySize, GEMM_SMEM);
        smem_set = 1;
    }

    // init (wsplit + deg zero + counters), degree count
    k_init<<<(NPAD + 255) / 256, 256>>>(W[1], W[2], W[3], N);
    k_count<<<(E + 255) / 256, 256>>>(ei_words, E);

    // fused scan (rowptr/cursor/dis/s1), CSR fill
    k_scan<<<NB, 1024>>>(pos, N);
    k_fill<<<(E + 255) / 256, 256>>>(ei_words, E);

    // layer 0 (fused 3-wide agg + dense W0 + bias + silu + dis fold) -> fp16 x~
    k_layer0<<<(N * 32 + 255) / 256, 256>>>(s1, W[0], B[0], xbuf, N);

    // layers 1..3: TC GEMM (smem B + cp.async A pipeline) then fp16 aggregation
    int gemm_blocks = NPAD / 128;            // 392
    int agg_blocks = (N * 16 + 255) / 256;   // 16 lanes per node
    for (int l = 1; l <= 3; l++) {
        k_gemm128_tc<<<gemm_blocks, 256, GEMM_SMEM>>>(xbuf, bh3 + (l - 1) * HD * HD,
                                                      bl3 + (l - 1) * HD * HD, hsbuf);
        k_agg128<<<agg_blocks, 256>>>(hsbuf, B[l], xbuf, N);
    }

    // fused tail: hs3 GEMM + grid sync + 3-wide aggregation -> out
    k_tail<<<TAIL_BLOCKS, 256>>>(xbuf, W[4], B[4], s1, (float*)d_out, N);
}